// round 11
// baseline (speedup 1.0000x reference)
#include <cuda_runtime.h>

#define BB   4
#define NN   8192
#define CCH  64
#define NPTS (BB*NN)          // 32768
#define KLn  12
#define EPSbn 1e-5f
#define G_STAT 1024
#define G_CONV 1184
#define MT   96               // conv2 edge-tile (divisible by 6 and 12)
#define BKT  1024             // x-buckets per batch
#define XLO  (-5.0f)
#define BWID (10.0f/1024.0f)
#define INVBW (1024.0f/10.0f)
#define WW   768              // half-window in sorted positions
#define WINMAX (128 + 2*WW)   // 1664

// ---------------- scratch (static device arrays; no allocation) ----------------
__device__ __align__(16) float  g_xt[NPTS*CCH];            // x transposed (B,N,C)   8MB
__device__ __align__(16) float4 g_pp[NPTS];                // packed points (x,y,z,|p|^2)
__device__ __align__(16) float4 g_pb[NPTS];                // bucket-sorted points
__device__             int    g_pidx[NPTS];                // bucketed pos -> orig n
__device__             int    g_p2b[NPTS];                 // bucketed pos -> bucket id
__device__             int    g_bcnt[BB*BKT];              // bucket counts
__device__             int    g_bfill[BB*BKT];             // bucket fill cursors
__device__             int    g_boff[BB*(BKT+1)];          // bucket offsets (per batch)
__device__             int    g_flag[NPTS];                // certificate-failed flags
__device__             int    g_idx[NPTS*KLn];             // 12 NN per point (sorted)
__device__ __align__(16) unsigned long long g_kk[13*NPTS]; // packed (d,idx) keys
__device__ __align__(16) float g_PQ[4][NPTS*CCH];          // P_s,Q_s,P_l,Q_l        32MB
__device__ __align__(16) float g_mx[NPTS*CCH];             // per-(pt,ch) max of h2   8MB
__device__ __align__(16) float g_mn[NPTS*CCH];             // per-(pt,ch) min of h2   8MB
__device__             float  g_part[2048*128];            // block partial stats
__device__             float  g_bnA[128];                  // layer1 scale/shift
__device__             float  g_bnB[128];                  // layer2 scale/shift
__device__ __align__(16) float g_Wf[4][4096];              // folded conv1 W, [k][o]
__device__ __align__(16) float g_W2t[2][4096];             // conv2 W transposed [k][o]

// ---------------- f32x2 helpers ----------------
__device__ __forceinline__ unsigned long long pk2(float lo, float hi) {
    unsigned long long r;
    asm("mov.b64 %0, {%1,%2};" : "=l"(r) : "f"(lo), "f"(hi));
    return r;
}
__device__ __forceinline__ unsigned long long dup2(float v) { return pk2(v, v); }
__device__ __forceinline__ void upk2(unsigned long long r, float& lo, float& hi) {
    asm("mov.b64 {%0,%1}, %2;" : "=f"(lo), "=f"(hi) : "l"(r));
}
__device__ __forceinline__ unsigned long long ffma2(unsigned long long a,
                                                    unsigned long long b,
                                                    unsigned long long c) {
    unsigned long long d;
    asm("fma.rn.f32x2 %0, %1, %2, %3;" : "=l"(d) : "l"(a), "l"(b), "l"(c));
    return d;
}

// monotone float->u32 (total order preserving, handles negatives)
__device__ __forceinline__ unsigned fmono(float f) {
    unsigned u = __float_as_uint(f);
    return u ^ ((u >> 31) ? 0xFFFFFFFFu : 0x80000000u);
}
__device__ __forceinline__ int xbucket(float x) {
    int bi = (int)floorf((x - XLO) * INVBW);
    return min(BKT-1, max(0, bi));
}

// ---------------- weight prep: fold conv1, transpose everything ----------------
__global__ void k_prep(const float* __restrict__ Ws1, const float* __restrict__ Wl1,
                       const float* __restrict__ Ws2, const float* __restrict__ Wl2)
{
    int t = blockIdx.x*blockDim.x + threadIdx.x;
    if (t < 4096) {
        int o = t >> 6, c = t & 63;
        float a0 = Ws1[o*128 + c],  a1 = Ws1[o*128 + 64 + c];
        g_Wf[0][c*64+o] = a0 - a1;          // Wa_s
        g_Wf[1][c*64+o] = a1;               // Wb_s
        float b0 = Wl1[o*128 + c],  b1 = Wl1[o*128 + 64 + c];
        g_Wf[2][c*64+o] = b0 - b1;          // Wa_l
        g_Wf[3][c*64+o] = b1;               // Wb_l
        g_W2t[0][c*64+o] = Ws2[o*64+c];
        g_W2t[1][c*64+o] = Wl2[o*64+c];
    }
}

// ---------------- pack pos into float4 ----------------
__global__ void k_pos(const float* __restrict__ pos)
{
    int t = blockIdx.x*blockDim.x + threadIdx.x;
    if (t < NPTS) {
        int n = t & (NN-1), b = t >> 13;
        float px = pos[(b*3+0)*NN + n];
        float py = pos[(b*3+1)*NN + n];
        float pz = pos[(b*3+2)*NN + n];
        g_pp[t] = make_float4(px, py, pz, px*px + py*py + pz*pz);
    }
}

// ---------------- coalesced tiled transpose of x ----------------
__global__ __launch_bounds__(256) void k_pack(const float* __restrict__ x)
{
    __shared__ float tile[32][33];
    int b  = blockIdx.z;
    int c0 = blockIdx.y * 32;
    int n0 = blockIdx.x * 32;
    int tx = threadIdx.x & 31, ty = threadIdx.x >> 5;   // ty 0..7
#pragma unroll
    for (int i = 0; i < 4; i++) {
        int r = ty + 8*i;                               // channel row
        tile[r][tx] = x[((size_t)(b*CCH + c0 + r))*NN + n0 + tx];
    }
    __syncthreads();
#pragma unroll
    for (int i = 0; i < 4; i++) {
        int r = ty + 8*i;                               // n row
        g_xt[((size_t)(b*NN + n0 + r))*64 + c0 + tx] = tile[tx][r];
    }
}

// ---------------- bucketing: zero, count, scan, fill ----------------
__global__ void k_bzero()
{
    int t = blockIdx.x*blockDim.x + threadIdx.x;
    if (t < BB*BKT) { g_bcnt[t] = 0; g_bfill[t] = 0; }
}
__global__ void k_bcount()
{
    int t = blockIdx.x*blockDim.x + threadIdx.x;
    if (t < NPTS) {
        int b = t >> 13;
        atomicAdd(&g_bcnt[b*BKT + xbucket(g_pp[t].x)], 1);
    }
}
__global__ __launch_bounds__(BKT) void k_bscan()
{
    __shared__ int sm[BKT];
    int b = blockIdx.x, t = threadIdx.x;
    sm[t] = g_bcnt[b*BKT + t];
    __syncthreads();
    for (int off = 1; off < BKT; off <<= 1) {
        int v = (t >= off) ? sm[t-off] : 0;
        __syncthreads();
        sm[t] += v;
        __syncthreads();
    }
    g_boff[b*(BKT+1) + t + 1] = sm[t];       // inclusive -> shifted = exclusive
    if (t == 0) g_boff[b*(BKT+1)] = 0;
}
__global__ void k_bfill()
{
    int t = blockIdx.x*blockDim.x + threadIdx.x;
    if (t < NPTS) {
        int b = t >> 13, n = t & (NN-1);
        float4 p = g_pp[t];
        int bi = xbucket(p.x);
        int pos = g_boff[b*(BKT+1) + bi] + atomicAdd(&g_bfill[b*BKT + bi], 1);
        g_pb[b*NN + pos]   = p;
        g_pidx[b*NN + pos] = n;
        g_p2b[b*NN + pos]  = bi;
    }
}

// ---------------- windowed KNN: one fixed shared window + certificate -------
// Block: 128 consecutive bucketed queries. Window = [C0-WW, C0+128+WW) clamped,
// staged once in shared. Phase A: dist-only FMNMX top-13 (incl self) in the
// shifted metric d~ = d^2 - |q|^2. Certificate: bucket-edge bound on both
// sides; failures flagged for exact fallback. Phase B: rescan window with
// thr = bd[12], emit up to 13 (d,idx) keys.
#define KINS(dv)                                                   \
    if ((dv) < bd[12]) {                                           \
        float tt = (dv);                                           \
        _Pragma("unroll")                                          \
        for (int jj = 0; jj < 13; jj++) {                          \
            float lo = fminf(bd[jj], tt);                          \
            tt = fmaxf(bd[jj], tt);                                \
            bd[jj] = lo;                                           \
        }                                                          \
    }

__global__ __launch_bounds__(128) void k_knnw()
{
    __shared__ __align__(16) float4 win[WINMAX];
    int t  = threadIdx.x;
    int C0 = blockIdx.x * 128;
    int P  = C0 + t;
    int b  = P >> 13;
    int blo = b*NN, bhi = blo + NN;
    int W0 = max(blo, C0 - WW);
    int W1 = min(bhi, C0 + 128 + WW);
    int n  = W1 - W0;

    for (int i = t; i < n; i += 128) win[i] = g_pb[W0 + i];
    __syncthreads();

    int sp = P - W0;                       // self position in window
    float4 qp = win[sp];
    float qx = -2.f*qp.x, qy = -2.f*qp.y, qz = -2.f*qp.z;
    float qw = qp.w;

    float bd[13];
#pragma unroll
    for (int i = 0; i < 13; i++) bd[i] = 3.4e38f;

    // ---- phase A: top-13 (incl self) over the window ----
    int c0 = 0;
#pragma unroll 1
    for (; c0 + 4 <= n; c0 += 4) {
        float4 p0 = win[c0+0], p1 = win[c0+1];
        float4 p2 = win[c0+2], p3 = win[c0+3];
        float d0 = fmaf(qx,p0.x, fmaf(qy,p0.y, fmaf(qz,p0.z, p0.w)));
        float d1 = fmaf(qx,p1.x, fmaf(qy,p1.y, fmaf(qz,p1.z, p1.w)));
        float d2 = fmaf(qx,p2.x, fmaf(qy,p2.y, fmaf(qz,p2.z, p2.w)));
        float d3 = fmaf(qx,p3.x, fmaf(qy,p3.y, fmaf(qz,p3.z, p3.w)));
        float m = fminf(fminf(d0,d1), fminf(d2,d3));
        if (m < bd[12]) { KINS(d0); KINS(d1); KINS(d2); KINS(d3); }
    }
#pragma unroll 1
    for (; c0 < n; c0++) {
        float4 p = win[c0];
        float d = fmaf(qx,p.x, fmaf(qy,p.y, fmaf(qz,p.z, p.w)));
        KINS(d);
    }
    float thr = bd[12];

    // ---- certificate: excluded points cannot beat thr (bucket-edge bound) ----
    bool certL = (W0 == blo);
    if (!certL) {
        float bx = XLO + (g_p2b[W0-1] + 1)*BWID;   // upper edge of W0-1's bucket
        float dx = qp.x - bx;
        certL = (dx > 0.f) && (fmaf(dx, dx, -qw) >= thr);
    }
    bool certR = (W1 == bhi);
    if (!certR) {
        float bx = XLO + g_p2b[W1]*BWID;           // lower edge of W1's bucket
        float dx = bx - qp.x;
        certR = (dx > 0.f) && (fmaf(dx, dx, -qw) >= thr);
    }
    int qorig = blo + g_pidx[P];
    g_flag[qorig] = (certL && certR) ? 0 : 1;

    // ---- phase B: rescan window, emit keys (exclude self) ----
    int cnt = 0;
#pragma unroll 1
    for (c0 = 0; c0 + 4 <= n; c0 += 4) {
        float4 p0 = win[c0+0], p1 = win[c0+1];
        float4 p2 = win[c0+2], p3 = win[c0+3];
        float d0 = fmaf(qx,p0.x, fmaf(qy,p0.y, fmaf(qz,p0.z, p0.w)));
        float d1 = fmaf(qx,p1.x, fmaf(qy,p1.y, fmaf(qz,p1.z, p1.w)));
        float d2 = fmaf(qx,p2.x, fmaf(qy,p2.y, fmaf(qz,p2.z, p2.w)));
        float d3 = fmaf(qx,p3.x, fmaf(qy,p3.y, fmaf(qz,p3.z, p3.w)));
        float m = fminf(fminf(d0,d1), fminf(d2,d3));
        if (m <= thr) {
            float dd[4] = {d0, d1, d2, d3};
#pragma unroll
            for (int u = 0; u < 4; u++) {
                int i = c0 + u;
                if (dd[u] <= thr && i != sp && cnt < 13) {
                    g_kk[cnt*NPTS + qorig] =
                        ((unsigned long long)fmono(dd[u]) << 13)
                        | (unsigned)g_pidx[W0 + i];
                    cnt++;
                }
            }
        }
    }
#pragma unroll 1
    for (; c0 < n; c0++) {
        float4 p = win[c0];
        float d = fmaf(qx,p.x, fmaf(qy,p.y, fmaf(qz,p.z, p.w)));
        if (d <= thr && c0 != sp && cnt < 13) {
            g_kk[cnt*NPTS + qorig] =
                ((unsigned long long)fmono(d) << 13)
                | (unsigned)g_pidx[W0 + c0];
            cnt++;
        }
    }
#pragma unroll 1
    for (int r = cnt; r < 13; r++)
        g_kk[r*NPTS + qorig] = ~0ULL;
}

// ---------------- exact fallback: one warp per flagged query ----------------
__global__ __launch_bounds__(128) void k_knnfb()
{
    __shared__ unsigned long long fbs[4][32][14];
    int t = threadIdx.x;
    int wid = t >> 5, lane = t & 31;
    int qbase = (blockIdx.x*4 + wid) * 32;
    unsigned mask = __ballot_sync(0xffffffffu, g_flag[qbase + lane] != 0);
    while (mask) {
        int bit = __ffs(mask) - 1;
        mask &= mask - 1;
        int q = qbase + bit;
        int b = q >> 13, blo = b*NN, qn = q & (NN-1);
        float4 qp = g_pp[q];
        float qx = -2.f*qp.x, qy = -2.f*qp.y, qz = -2.f*qp.z;

        unsigned long long top[13];
#pragma unroll
        for (int r = 0; r < 13; r++) top[r] = ~0ULL;
#pragma unroll 1
        for (int i = lane; i < NN; i += 32) {
            if (i == qn) continue;
            float4 c = g_pp[blo + i];
            float d = fmaf(qx,c.x, fmaf(qy,c.y, fmaf(qz,c.z, c.w)));
            unsigned long long key =
                ((unsigned long long)fmono(d) << 13) | (unsigned)i;
            if (key < top[12]) {
                unsigned long long tt = key;
#pragma unroll
                for (int j = 0; j < 13; j++) {
                    unsigned long long lo = (top[j] < tt) ? top[j] : tt;
                    unsigned long long hi = (top[j] < tt) ? tt : top[j];
                    top[j] = lo; tt = hi;
                }
            }
        }
#pragma unroll
        for (int r = 0; r < 13; r++) fbs[wid][lane][r] = top[r];
        fbs[wid][lane][13] = ~0ULL;
        __syncwarp();

        int ptr = 0;
#pragma unroll 1
        for (int r = 0; r < 13; r++) {
            unsigned long long head = fbs[wid][lane][ptr];
            unsigned long long mn = head;
#pragma unroll
            for (int off = 16; off > 0; off >>= 1) {
                unsigned long long o = __shfl_xor_sync(0xffffffffu, mn, off);
                if (o < mn) mn = o;
            }
            unsigned who = __ballot_sync(0xffffffffu, head == mn);
            if (lane == __ffs(who) - 1) ptr = min(ptr + 1, 13);
            if (lane == 0) g_kk[r*NPTS + q] = mn;
        }
        __syncwarp();
    }
}

// ---------------- KNN select+sort: 12 smallest of 13 keys per query --------
__global__ __launch_bounds__(256) void k_knn3()
{
    int q = blockIdx.x*256 + threadIdx.x;
    unsigned long long best[12];
#pragma unroll
    for (int r = 0; r < 12; r++) best[r] = ~0ULL;
#pragma unroll 1
    for (int r = 0; r < 13; r++) {
        unsigned long long key = g_kk[r*NPTS + q];
        if (key < best[11]) {
            unsigned long long tt = key;
#pragma unroll
            for (int j = 0; j < 12; j++) {
                unsigned long long lo = (best[j] < tt) ? best[j] : tt;
                unsigned long long hi = (best[j] < tt) ? tt : best[j];
                best[j] = lo; tt = hi;
            }
        }
    }
#pragma unroll
    for (int r = 0; r < 12; r++)
        g_idx[q*KLn + r] = (int)(best[r] & 8191u);
}

// ---------------- P/Q GEMM with f32x2 FMA ----------------
__global__ __launch_bounds__(128) void k_pq()
{
    __shared__ __align__(16) float Ws[4096];
    __shared__ __align__(16) float Us[4096];
    int w = blockIdx.y;
    int t = threadIdx.x;
    for (int i = t; i < 4096; i += 128) Ws[i] = g_Wf[w][i];

    int base = blockIdx.x * 64;
    {   // stage X tile k-major with xor swizzle
        int e = t >> 1, h = t & 1;
        const float4* src = (const float4*)&g_xt[(base + e)*64 + h*32];
        int gg = e >> 2, eo = e & 3;
#pragma unroll
        for (int c4 = 0; c4 < 8; c4++) {
            float4 v = src[c4];
            int c = h*32 + c4*4;
            Us[(c+0)*64 + ((gg ^ ((c+0)&15))<<2) + eo] = v.x;
            Us[(c+1)*64 + ((gg ^ ((c+1)&15))<<2) + eo] = v.y;
            Us[(c+2)*64 + ((gg ^ ((c+2)&15))<<2) + eo] = v.z;
            Us[(c+3)*64 + ((gg ^ ((c+3)&15))<<2) + eo] = v.w;
        }
    }
    __syncthreads();

    int tx = t & 15, ty = t >> 4;
    unsigned long long acc2[4][4];             // [oi-pair][mi]
#pragma unroll
    for (int i = 0; i < 4; i++)
#pragma unroll
        for (int j = 0; j < 4; j++) acc2[i][j] = 0ULL;

#pragma unroll 8
    for (int k = 0; k < 64; k++) {
        const unsigned long long* ap = (const unsigned long long*)&Ws[k*64 + ty*8];
        unsigned long long a2[4] = {ap[0], ap[1], ap[2], ap[3]};
        float4 bf = *(const float4*)&Us[k*64 + ((tx ^ (k&15))<<2)];
        unsigned long long b2[4] = {dup2(bf.x), dup2(bf.y), dup2(bf.z), dup2(bf.w)};
#pragma unroll
        for (int oi = 0; oi < 4; oi++)
#pragma unroll
            for (int mi = 0; mi < 4; mi++)
                acc2[oi][mi] = ffma2(a2[oi], b2[mi], acc2[oi][mi]);
    }

    float* out = g_PQ[w];
#pragma unroll
    for (int mi = 0; mi < 4; mi++) {
        float a[8];
#pragma unroll
        for (int oi = 0; oi < 4; oi++) upk2(acc2[oi][mi], a[2*oi], a[2*oi+1]);
        int pt = base + tx*4 + mi;
        *(float4*)&out[pt*64 + ty*8]     = make_float4(a[0],a[1],a[2],a[3]);
        *(float4*)&out[pt*64 + ty*8 + 4] = make_float4(a[4],a[5],a[6],a[7]);
    }
}

// ---------------- stats of h1 = P[i]+Q[j] over all edges ----------------
template<int K>
__global__ __launch_bounds__(256) void k_stats1()
{
    const float* __restrict__ P = g_PQ[(K==6)?0:2];
    const float* __restrict__ Q = g_PQ[(K==6)?1:3];
    const int M = NPTS*K;
    int warp = threadIdx.x >> 5, lane = threadIdx.x & 31;
    int gw = blockIdx.x*8 + warp, nw = G_STAT*8;
    float s0=0, ss0=0, s1=0, ss1=0;
    for (int m = gw; m < M; m += nw) {
        int kk = m % K, bn = m / K;
        int j  = g_idx[bn*KLn + kk];
        int b  = bn >> 13;
        const float* Pp = &P[bn*64];
        const float* Qp = &Q[(b*NN + j)*64];
        float v0 = Pp[lane]      + Qp[lane];
        float v1 = Pp[lane + 32] + Qp[lane + 32];
        s0 += v0; ss0 = fmaf(v0, v0, ss0);
        s1 += v1; ss1 = fmaf(v1, v1, ss1);
    }
    __shared__ float stg[8][128];
    stg[warp][lane]      = s0;  stg[warp][64+lane] = ss0;
    stg[warp][32+lane]   = s1;  stg[warp][96+lane] = ss1;
    __syncthreads();
    int t = threadIdx.x;
    if (t < 128) {
        float a = 0;
#pragma unroll
        for (int w2 = 0; w2 < 8; w2++) a += stg[w2][t];
        g_part[blockIdx.x*128 + t] = a;
    }
}

// ---------------- finalize BN params (parallel, deterministic) ----------------
__global__ __launch_bounds__(256) void k_reduce(int G, float invM,
                         const float* __restrict__ gamma,
                         const float* __restrict__ beta, int which)
{
    __shared__ float sm[8][64];
    int t = threadIdx.x;
    int c = t & 63, grp = t >> 6;              // 4 groups
    int chunk = (G + 3) >> 2;
    int g0 = grp*chunk, g1 = min(G, g0 + chunk);
    float S = 0.f, SS = 0.f;
    for (int g = g0; g < g1; g++) { S += g_part[g*128 + c]; SS += g_part[g*128 + 64 + c]; }
    sm[grp][c] = S; sm[4+grp][c] = SS;
    __syncthreads();
    if (t < 64) {
        float Sa = 0.f, SSa = 0.f;
#pragma unroll
        for (int g = 0; g < 4; g++) { Sa += sm[g][t]; SSa += sm[4+g][t]; }
        float mean = Sa * invM;
        float var  = SSa * invM - mean*mean;
        float sc   = gamma[t] * rsqrtf(var + EPSbn);
        float sh   = beta[t] - mean*sc;
        float* dst = which ? g_bnB : g_bnA;
        dst[t] = sc; dst[64+t] = sh;
    }
}

// ---------------- conv2: 96-edge tiles, f32x2 GEMM, fused min/max over k ----------------
template<int K>
__global__ __launch_bounds__(128) void k_conv2()
{
    const float* __restrict__ P   = g_PQ[(K==6)?0:2];
    const float* __restrict__ Q   = g_PQ[(K==6)?1:3];
    const float* __restrict__ W2t = g_W2t[(K==6)?0:1];
    const int nTiles = (NPTS*K)/MT;
    const int PPT = MT/K;                      // whole points per tile

    __shared__ __align__(16) float Ws[4096];
    __shared__ __align__(16) float Ub[6336];   // union: Us 64x97 / h2s 96x66
    __shared__ float bnsc[64], bnsh[64];
    __shared__ float blockS[64], blockSS[64];
    int t = threadIdx.x;
    for (int i = t; i < 4096; i += 128) Ws[i] = W2t[i];
    if (t < 64) { bnsc[t] = g_bnA[t]; bnsh[t] = g_bnA[64+t]; }
    __syncthreads();

    int tx = t & 15, ty = t >> 4;
    float accS[8], accSS[8];
#pragma unroll
    for (int i = 0; i < 8; i++) { accS[i] = 0.f; accSS[i] = 0.f; }

    for (int tile = blockIdx.x; tile < nTiles; tile += G_CONV) {
        int mbase = tile * MT;
        __syncthreads();                       // Ub reuse guard
        // gather + BN1 + ReLU -> Us (k-major, row stride 97)
        for (int u = t; u < 2*MT; u += 128) {
            int e = u >> 1, h = u & 1;
            int m = mbase + e;
            int kk = m % K, bn = m / K;
            int j  = g_idx[bn*KLn + kk];
            int b  = bn >> 13;
            const float4* Pp = (const float4*)&P[bn*64 + h*32];
            const float4* Qp = (const float4*)&Q[(b*NN + j)*64 + h*32];
#pragma unroll
            for (int c4 = 0; c4 < 8; c4++) {
                float4 pv = Pp[c4], qv = Qp[c4];
                int c = h*32 + c4*4;
                Ub[(c+0)*97 + e] = fmaxf(0.f, fmaf(pv.x+qv.x, bnsc[c+0], bnsh[c+0]));
                Ub[(c+1)*97 + e] = fmaxf(0.f, fmaf(pv.y+qv.y, bnsc[c+1], bnsh[c+1]));
                Ub[(c+2)*97 + e] = fmaxf(0.f, fmaf(pv.z+qv.z, bnsc[c+2], bnsh[c+2]));
                Ub[(c+3)*97 + e] = fmaxf(0.f, fmaf(pv.w+qv.w, bnsc[c+3], bnsh[c+3]));
            }
        }
        __syncthreads();

        // GEMM: edges e = tx + 16*mi (mi<6), channels ty*8..ty*8+7 (as 4 pairs)
        unsigned long long acc2[4][6];
#pragma unroll
        for (int i = 0; i < 4; i++)
#pragma unroll
            for (int j2 = 0; j2 < 6; j2++) acc2[i][j2] = 0ULL;

#pragma unroll 8
        for (int k = 0; k < 64; k++) {
            const unsigned long long* ap = (const unsigned long long*)&Ws[k*64 + ty*8];
            unsigned long long a2[4] = {ap[0], ap[1], ap[2], ap[3]};
            unsigned long long b2[6];
#pragma unroll
            for (int mi = 0; mi < 6; mi++)
                b2[mi] = dup2(Ub[k*97 + tx + 16*mi]);
#pragma unroll
            for (int oi = 0; oi < 4; oi++)
#pragma unroll
                for (int mi = 0; mi < 6; mi++)
                    acc2[oi][mi] = ffma2(a2[oi], b2[mi], acc2[oi][mi]);
        }
        __syncthreads();                       // Us dead; reuse Ub for h2s

        // unpack: stats accumulation + write h2 tile to shared (row stride 66)
#pragma unroll
        for (int mi = 0; mi < 6; mi++) {
            int e = tx + 16*mi;
            float v[8];
#pragma unroll
            for (int oi = 0; oi < 4; oi++) upk2(acc2[oi][mi], v[2*oi], v[2*oi+1]);
#pragma unroll
            for (int oi = 0; oi < 8; oi++) {
                accS[oi]  += v[oi];
                accSS[oi] = fmaf(v[oi], v[oi], accSS[oi]);
            }
#pragma unroll
            for (int oi = 0; oi < 4; oi++)
                *(float2*)&Ub[e*66 + ty*8 + 2*oi] = make_float2(v[2*oi], v[2*oi+1]);
        }
        __syncthreads();

        // per-(point,channel) min/max over K edges (tile holds whole points)
        for (int s = t; s < PPT*64; s += 128) {
            int p = s >> 6, ch = s & 63;
            float vmax = -3.4e38f, vmin = 3.4e38f;
#pragma unroll
            for (int kk = 0; kk < K; kk++) {
                float v = Ub[(p*K + kk)*66 + ch];
                vmax = fmaxf(vmax, v); vmin = fminf(vmin, v);
            }
            int pt = mbase/K + p;
            g_mx[pt*64 + ch] = vmax;
            g_mn[pt*64 + ch] = vmin;
        }
    }

    // cross-thread stats reduce over tx lanes
#pragma unroll
    for (int off = 1; off < 16; off <<= 1)
#pragma unroll
        for (int oi = 0; oi < 8; oi++) {
            accS[oi]  += __shfl_xor_sync(0xffffffffu, accS[oi],  off);
            accSS[oi] += __shfl_xor_sync(0xffffffffu, accSS[oi], off);
        }
    if (tx == 0)
#pragma unroll
        for (int oi = 0; oi < 8; oi++) { blockS[ty*8+oi] = accS[oi]; blockSS[ty*8+oi] = accSS[oi]; }
    __syncthreads();
    if (t < 128)
        g_part[blockIdx.x*128 + t] = (t < 64) ? blockS[t] : blockSS[t-64];
}

// ---------------- BN2 + ReLU + max -> output (from min/max buffers) ----------------
template<int K>
__global__ __launch_bounds__(256) void k_out(float* __restrict__ out)
{
    const int chOff = (K==6) ? 0 : 64;
    __shared__ float res[64][33];
    int t = threadIdx.x;
    int warp = t >> 5, lane = t & 31;
    int bn0 = blockIdx.x * 32;
    int b = bn0 >> 13, n0 = bn0 & (NN-1);
    float sc0 = g_bnB[lane],      sh0 = g_bnB[64+lane];
    float sc1 = g_bnB[lane + 32], sh1 = g_bnB[96+lane];
#pragma unroll
    for (int i = 0; i < 4; i++) {
        int nl = warp*4 + i;
        int pt = bn0 + nl;
        float h0 = (sc0 >= 0.f) ? g_mx[pt*64 + lane]      : g_mn[pt*64 + lane];
        float h1 = (sc1 >= 0.f) ? g_mx[pt*64 + lane + 32] : g_mn[pt*64 + lane + 32];
        res[lane][nl]      = fmaxf(0.f, fmaf(h0, sc0, sh0));
        res[lane + 32][nl] = fmaxf(0.f, fmaf(h1, sc1, sh1));
    }
    __syncthreads();
#pragma unroll
    for (int i = 0; i < 8; i++) {
        int id = t + i*256;
        int r = id >> 5, col = id & 31;
        out[((size_t)b*128 + chOff + r)*NN + n0 + col] = res[r][col];
    }
}

// ---------------- launch ----------------
extern "C" void kernel_launch(void* const* d_in, const int* in_sizes, int n_in,
                              void* d_out, int out_size)
{
    const float* x    = (const float*)d_in[0];
    const float* pos  = (const float*)d_in[1];
    const float* Ws1  = (const float*)d_in[2];
    const float* gs1  = (const float*)d_in[4];
    const float* ts1  = (const float*)d_in[5];
    const float* Ws2  = (const float*)d_in[6];
    const float* gs2  = (const float*)d_in[8];
    const float* ts2  = (const float*)d_in[9];
    const float* Wl1  = (const float*)d_in[10];
    const float* gl1  = (const float*)d_in[12];
    const float* tl1  = (const float*)d_in[13];
    const float* Wl2  = (const float*)d_in[14];
    const float* gl2  = (const float*)d_in[16];
    const float* tl2  = (const float*)d_in[17];
    float* out = (float*)d_out;

    k_prep<<<16, 256>>>(Ws1, Wl1, Ws2, Wl2);
    k_pos<<<NPTS/256, 256>>>(pos);
    k_pack<<<dim3(NN/32, 2, BB), 256>>>(x);

    // x-sort + windowed KNN + certificate fallback
    k_bzero<<<16, 256>>>();
    k_bcount<<<NPTS/256, 256>>>();
    k_bscan<<<BB, BKT>>>();
    k_bfill<<<NPTS/256, 256>>>();
    k_knnw<<<NPTS/128, 128>>>();
    k_knnfb<<<NPTS/128, 128>>>();
    k_knn3<<<NPTS/256, 256>>>();

    k_pq<<<dim3(NPTS/64, 4), 128>>>();

    // short stream (k=6), channels 0..63
    k_stats1<6><<<G_STAT, 256>>>();
    k_reduce<<<1, 256>>>(G_STAT, 1.f/(NPTS*6),  gs1, ts1, 0);
    k_conv2<6><<<G_CONV, 128>>>();
    k_reduce<<<1, 256>>>(G_CONV, 1.f/(NPTS*6),  gs2, ts2, 1);
    k_out<6><<<NPTS/32, 256>>>(out);

    // long stream (k=12), channels 64..127
    k_stats1<12><<<G_STAT, 256>>>();
    k_reduce<<<1, 256>>>(G_STAT, 1.f/(NPTS*12), gl1, tl1, 0);
    k_conv2<12><<<G_CONV, 128>>>();
    k_reduce<<<1, 256>>>(G_CONV, 1.f/(NPTS*12), gl2, tl2, 1);
    k_out<12><<<NPTS/32, 256>>>(out);
}

// round 13
// speedup vs baseline: 2.7405x; 2.7405x over previous
#include <cuda_runtime.h>

#define BB   4
#define NN   8192
#define CCH  64
#define NPTS (BB*NN)          // 32768
#define KLn  12
#define EPSbn 1e-5f
#define G_STAT 1024
#define G_CONV 1184
#define MT   96               // conv2 edge-tile (divisible by 6 and 12)
#define KCH4 512              // knn tile chunk per quarter (float4s)
#define QTR  2048             // candidates per quarter

// ---------------- scratch (static device arrays; no allocation) ----------------
__device__ __align__(16) float  g_xt[NPTS*CCH];            // x transposed (B,N,C)   8MB
__device__ __align__(16) float4 g_pp[NPTS];                // packed points (x,y,z,|p|^2)
__device__             int    g_idx[NPTS*KLn];             // 12 NN per point (sorted)
__device__ __align__(16) unsigned long long g_kk[52*NPTS]; // packed (d,idx) keys, 4x13
__device__ __align__(16) float g_PQ[4][NPTS*CCH];          // P_s,Q_s,P_l,Q_l        32MB
__device__ __align__(16) float g_mx[2][NPTS*CCH];          // per-stream h2 max     16MB
__device__ __align__(16) float g_mn[2][NPTS*CCH];          // per-stream h2 min     16MB
__device__             float  g_part[2*1184*128];          // per-stream block stats
__device__             float  g_bnA[256];                  // layer1 scale/shift (s,l)
__device__             float  g_bnB[256];                  // layer2 scale/shift (s,l)
__device__ __align__(16) float g_Wf[4][4096];              // folded conv1 W, [k][o]
__device__ __align__(16) float g_W2t[2][4096];             // conv2 W transposed [k][o]

// ---------------- f32x2 helpers ----------------
__device__ __forceinline__ unsigned long long pk2(float lo, float hi) {
    unsigned long long r;
    asm("mov.b64 %0, {%1,%2};" : "=l"(r) : "f"(lo), "f"(hi));
    return r;
}
__device__ __forceinline__ unsigned long long dup2(float v) { return pk2(v, v); }
__device__ __forceinline__ void upk2(unsigned long long r, float& lo, float& hi) {
    asm("mov.b64 {%0,%1}, %2;" : "=f"(lo), "=f"(hi) : "l"(r));
}
__device__ __forceinline__ unsigned long long ffma2(unsigned long long a,
                                                    unsigned long long b,
                                                    unsigned long long c) {
    unsigned long long d;
    asm("fma.rn.f32x2 %0, %1, %2, %3;" : "=l"(d) : "l"(a), "l"(b), "l"(c));
    return d;
}

// monotone float->u32 (total order preserving, handles negatives)
__device__ __forceinline__ unsigned fmono(float f) {
    unsigned u = __float_as_uint(f);
    return u ^ ((u >> 31) ? 0xFFFFFFFFu : 0x80000000u);
}

// ---------------- weight prep: fold conv1, transpose everything ----------------
__global__ void k_prep(const float* __restrict__ Ws1, const float* __restrict__ Wl1,
                       const float* __restrict__ Ws2, const float* __restrict__ Wl2)
{
    int t = blockIdx.x*blockDim.x + threadIdx.x;
    if (t < 4096) {
        int o = t >> 6, c = t & 63;
        float a0 = Ws1[o*128 + c],  a1 = Ws1[o*128 + 64 + c];
        g_Wf[0][c*64+o] = a0 - a1;          // Wa_s
        g_Wf[1][c*64+o] = a1;               // Wb_s
        float b0 = Wl1[o*128 + c],  b1 = Wl1[o*128 + 64 + c];
        g_Wf[2][c*64+o] = b0 - b1;          // Wa_l
        g_Wf[3][c*64+o] = b1;               // Wb_l
        g_W2t[0][c*64+o] = Ws2[o*64+c];
        g_W2t[1][c*64+o] = Wl2[o*64+c];
    }
}

// ---------------- pack pos into float4 ----------------
__global__ void k_pos(const float* __restrict__ pos)
{
    int t = blockIdx.x*blockDim.x + threadIdx.x;
    if (t < NPTS) {
        int n = t & (NN-1), b = t >> 13;
        float px = pos[(b*3+0)*NN + n];
        float py = pos[(b*3+1)*NN + n];
        float pz = pos[(b*3+2)*NN + n];
        g_pp[t] = make_float4(px, py, pz, px*px + py*py + pz*pz);
    }
}

// ---------------- coalesced tiled transpose of x ----------------
__global__ __launch_bounds__(256) void k_pack(const float* __restrict__ x)
{
    __shared__ float tile[32][33];
    int b  = blockIdx.z;
    int c0 = blockIdx.y * 32;
    int n0 = blockIdx.x * 32;
    int tx = threadIdx.x & 31, ty = threadIdx.x >> 5;   // ty 0..7
#pragma unroll
    for (int i = 0; i < 4; i++) {
        int r = ty + 8*i;                               // channel row
        tile[r][tx] = x[((size_t)(b*CCH + c0 + r))*NN + n0 + tx];
    }
    __syncthreads();
#pragma unroll
    for (int i = 0; i < 4; i++) {
        int r = ty + 8*i;                               // n row
        g_xt[((size_t)(b*NN + n0 + r))*64 + c0 + tx] = tile[tx][r];
    }
}

// ---------------- KNN, TPQ=4: 64 queries x 4 quarter-scanners per block ----
// Phase A: dist-only FMNMX top-13 (shifted metric) per quarter.
// Merge:   13-step 4-way merge of sorted lists -> exact global 13th (thr).
// Phase B: rescan own quarter, emit (d,idx) keys for d <= thr, excluding self.
#define KINS(dv)                                                   \
    if ((dv) < bd[12]) {                                           \
        float tt = (dv);                                           \
        _Pragma("unroll")                                          \
        for (int jj = 0; jj < 13; jj++) {                          \
            float lo = fminf(bd[jj], tt);                          \
            tt = fmaxf(bd[jj], tt);                                \
            bd[jj] = lo;                                           \
        }                                                          \
    }

__global__ __launch_bounds__(256) void k_knn1()
{
    __shared__ __align__(16) float4 tile[4][KCH4];   // 32KB
    __shared__ float sA[256*13];                     // 13.3KB sorted lists
    __shared__ float thrS[64];

    int t  = threadIdx.x;
    int ql = t & 63, h = t >> 6;                     // query-lane, quarter
    int q  = blockIdx.x*64 + ql;
    int b  = q >> 13;
    int nself = q & (NN-1);
    float4 qp = g_pp[q];
    float qx = -2.f*qp.x, qy = -2.f*qp.y, qz = -2.f*qp.z;
    int qbase = b*NN + h*QTR;

    float bd[13];
#pragma unroll
    for (int i = 0; i < 13; i++) bd[i] = 3.4e38f;

    // ---- phase A: per-quarter top-13 ----
    for (int cb = 0; cb < QTR; cb += KCH4) {
        __syncthreads();
        for (int i = ql; i < KCH4; i += 64)
            tile[h][i] = g_pp[qbase + cb + i];
        __syncthreads();
#pragma unroll 1
        for (int c0 = 0; c0 < KCH4; c0 += 4) {
            float4 p0 = tile[h][c0+0], p1 = tile[h][c0+1];
            float4 p2 = tile[h][c0+2], p3 = tile[h][c0+3];
            float d0 = fmaf(qx,p0.x, fmaf(qy,p0.y, fmaf(qz,p0.z, p0.w)));
            float d1 = fmaf(qx,p1.x, fmaf(qy,p1.y, fmaf(qz,p1.z, p1.w)));
            float d2 = fmaf(qx,p2.x, fmaf(qy,p2.y, fmaf(qz,p2.z, p2.w)));
            float d3 = fmaf(qx,p3.x, fmaf(qy,p3.y, fmaf(qz,p3.z, p3.w)));
            float m = fminf(fminf(d0,d1), fminf(d2,d3));
            if (m < bd[12]) { KINS(d0); KINS(d1); KINS(d2); KINS(d3); }
        }
    }

    // ---- exact global 13th via 4-way sorted merge ----
#pragma unroll
    for (int r = 0; r < 13; r++) sA[t*13 + r] = bd[r];
    __syncthreads();
    if (t < 64) {
        int i0 = 0, i1 = 0, i2 = 0, i3 = 0;
        float v = 0.f;
#pragma unroll
        for (int s = 0; s < 13; s++) {
            float a0 = sA[(t      )*13 + i0];
            float a1 = sA[(t +  64)*13 + i1];
            float a2 = sA[(t + 128)*13 + i2];
            float a3 = sA[(t + 192)*13 + i3];
            v = fminf(fminf(a0,a1), fminf(a2,a3));
            if      (v == a0) i0++;
            else if (v == a1) i1++;
            else if (v == a2) i2++;
            else              i3++;
        }
        thrS[t] = v;                          // 13th smallest incl. self
    }
    __syncthreads();
    float thr = thrS[ql];

    // ---- phase B: rescan own quarter, emit keys ----
    int cnt = 0;
    for (int cb = 0; cb < QTR; cb += KCH4) {
        __syncthreads();
        for (int i = ql; i < KCH4; i += 64)
            tile[h][i] = g_pp[qbase + cb + i];
        __syncthreads();
#pragma unroll 1
        for (int c0 = 0; c0 < KCH4; c0 += 4) {
            float4 p0 = tile[h][c0+0], p1 = tile[h][c0+1];
            float4 p2 = tile[h][c0+2], p3 = tile[h][c0+3];
            float d0 = fmaf(qx,p0.x, fmaf(qy,p0.y, fmaf(qz,p0.z, p0.w)));
            float d1 = fmaf(qx,p1.x, fmaf(qy,p1.y, fmaf(qz,p1.z, p1.w)));
            float d2 = fmaf(qx,p2.x, fmaf(qy,p2.y, fmaf(qz,p2.z, p2.w)));
            float d3 = fmaf(qx,p3.x, fmaf(qy,p3.y, fmaf(qz,p3.z, p3.w)));
            float m = fminf(fminf(d0,d1), fminf(d2,d3));
            if (m <= thr) {
                float dd[4] = {d0, d1, d2, d3};
#pragma unroll
                for (int u = 0; u < 4; u++) {
                    if (dd[u] <= thr) {
                        int j = h*QTR + cb + c0 + u;
                        if (j != nself && cnt < 13) {
                            g_kk[(h*13 + cnt)*NPTS + q] =
                                ((unsigned long long)fmono(dd[u]) << 13)
                                | (unsigned)j;
                            cnt++;
                        }
                    }
                }
            }
        }
    }
#pragma unroll 1
    for (int r = cnt; r < 13; r++)
        g_kk[(h*13 + r)*NPTS + q] = ~0ULL;     // pad
}

// ---------------- KNN select+sort: 12 smallest of 52 keys per query --------
__global__ __launch_bounds__(256) void k_knn3()
{
    int q = blockIdx.x*256 + threadIdx.x;
    unsigned long long best[12];
#pragma unroll
    for (int r = 0; r < 12; r++) best[r] = ~0ULL;
#pragma unroll 1
    for (int r = 0; r < 52; r++) {
        unsigned long long key = g_kk[r*NPTS + q];
        if (key < best[11]) {
            unsigned long long tt = key;
#pragma unroll
            for (int j = 0; j < 12; j++) {
                unsigned long long lo = (best[j] < tt) ? best[j] : tt;
                unsigned long long hi = (best[j] < tt) ? tt : best[j];
                best[j] = lo; tt = hi;
            }
        }
    }
#pragma unroll
    for (int r = 0; r < 12; r++)
        g_idx[q*KLn + r] = (int)(best[r] & 8191u);
}

// ---------------- P/Q GEMM with f32x2 FMA ----------------
__global__ __launch_bounds__(128) void k_pq()
{
    __shared__ __align__(16) float Ws[4096];
    __shared__ __align__(16) float Us[4096];
    int w = blockIdx.y;
    int t = threadIdx.x;
    for (int i = t; i < 4096; i += 128) Ws[i] = g_Wf[w][i];

    int base = blockIdx.x * 64;
    {   // stage X tile k-major with xor swizzle
        int e = t >> 1, h = t & 1;
        const float4* src = (const float4*)&g_xt[(base + e)*64 + h*32];
        int gg = e >> 2, eo = e & 3;
#pragma unroll
        for (int c4 = 0; c4 < 8; c4++) {
            float4 v = src[c4];
            int c = h*32 + c4*4;
            Us[(c+0)*64 + ((gg ^ ((c+0)&15))<<2) + eo] = v.x;
            Us[(c+1)*64 + ((gg ^ ((c+1)&15))<<2) + eo] = v.y;
            Us[(c+2)*64 + ((gg ^ ((c+2)&15))<<2) + eo] = v.z;
            Us[(c+3)*64 + ((gg ^ ((c+3)&15))<<2) + eo] = v.w;
        }
    }
    __syncthreads();

    int tx = t & 15, ty = t >> 4;
    unsigned long long acc2[4][4];             // [oi-pair][mi]
#pragma unroll
    for (int i = 0; i < 4; i++)
#pragma unroll
        for (int j = 0; j < 4; j++) acc2[i][j] = 0ULL;

#pragma unroll 8
    for (int k = 0; k < 64; k++) {
        const unsigned long long* ap = (const unsigned long long*)&Ws[k*64 + ty*8];
        unsigned long long a2[4] = {ap[0], ap[1], ap[2], ap[3]};
        float4 bf = *(const float4*)&Us[k*64 + ((tx ^ (k&15))<<2)];
        unsigned long long b2[4] = {dup2(bf.x), dup2(bf.y), dup2(bf.z), dup2(bf.w)};
#pragma unroll
        for (int oi = 0; oi < 4; oi++)
#pragma unroll
            for (int mi = 0; mi < 4; mi++)
                acc2[oi][mi] = ffma2(a2[oi], b2[mi], acc2[oi][mi]);
    }

    float* out = g_PQ[w];
#pragma unroll
    for (int mi = 0; mi < 4; mi++) {
        float a[8];
#pragma unroll
        for (int oi = 0; oi < 4; oi++) upk2(acc2[oi][mi], a[2*oi], a[2*oi+1]);
        int pt = base + tx*4 + mi;
        *(float4*)&out[pt*64 + ty*8]     = make_float4(a[0],a[1],a[2],a[3]);
        *(float4*)&out[pt*64 + ty*8 + 4] = make_float4(a[4],a[5],a[6],a[7]);
    }
}

// ---------------- fused stats of h1 = P[i]+Q[j] (both streams) -------------
template<int K>
__device__ __forceinline__ void stats_body(const float* __restrict__ P,
                                           const float* __restrict__ Q,
                                           float* __restrict__ part,
                                           float (*stg)[128])
{
    const int M = NPTS*K;
    int warp = threadIdx.x >> 5, lane = threadIdx.x & 31;
    int gw = blockIdx.x*8 + warp, nw = G_STAT*8;
    float s0=0, ss0=0, s1=0, ss1=0;
    for (int m = gw; m < M; m += nw) {
        int kk = m % K, bn = m / K;
        int j  = g_idx[bn*KLn + kk];
        int b  = bn >> 13;
        const float* Pp = &P[bn*64];
        const float* Qp = &Q[(b*NN + j)*64];
        float v0 = Pp[lane]      + Qp[lane];
        float v1 = Pp[lane + 32] + Qp[lane + 32];
        s0 += v0; ss0 = fmaf(v0, v0, ss0);
        s1 += v1; ss1 = fmaf(v1, v1, ss1);
    }
    stg[warp][lane]      = s0;  stg[warp][64+lane] = ss0;
    stg[warp][32+lane]   = s1;  stg[warp][96+lane] = ss1;
    __syncthreads();
    int t = threadIdx.x;
    if (t < 128) {
        float a = 0;
#pragma unroll
        for (int w2 = 0; w2 < 8; w2++) a += stg[w2][t];
        part[blockIdx.x*128 + t] = a;
    }
}
__global__ __launch_bounds__(256) void k_statsF()
{
    __shared__ float stg[8][128];
    if (blockIdx.y == 0) stats_body<6> (g_PQ[0], g_PQ[1], g_part, stg);
    else                 stats_body<12>(g_PQ[2], g_PQ[3], g_part + G_STAT*128, stg);
}

// ---------------- fused BN finalize (both streams, one layer) --------------
__global__ __launch_bounds__(256) void k_reduceF(int G, int partStride,
                         float invM0, float invM1,
                         const float* __restrict__ g0, const float* __restrict__ t0,
                         const float* __restrict__ g1, const float* __restrict__ t1,
                         int which)
{
    __shared__ float sm[8][64];
    int y = blockIdx.x;                        // stream 0=s, 1=l
    const float* part = g_part + y*partStride;
    float invM = y ? invM1 : invM0;
    const float* gamma = y ? g1 : g0;
    const float* beta  = y ? t1 : t0;
    int t = threadIdx.x;
    int c = t & 63, grp = t >> 6;              // 4 groups
    int chunk = (G + 3) >> 2;
    int gg0 = grp*chunk, gg1 = min(G, gg0 + chunk);
    float S = 0.f, SS = 0.f;
    for (int g = gg0; g < gg1; g++) { S += part[g*128 + c]; SS += part[g*128 + 64 + c]; }
    sm[grp][c] = S; sm[4+grp][c] = SS;
    __syncthreads();
    if (t < 64) {
        float Sa = 0.f, SSa = 0.f;
#pragma unroll
        for (int g = 0; g < 4; g++) { Sa += sm[g][t]; SSa += sm[4+g][t]; }
        float mean = Sa * invM;
        float var  = SSa * invM - mean*mean;
        float sc   = gamma[t] * rsqrtf(var + EPSbn);
        float sh   = beta[t] - mean*sc;
        float* dst = (which ? g_bnB : g_bnA) + y*128;
        dst[t] = sc; dst[64+t] = sh;
    }
}

// ---------------- fused conv2 (both streams): f32x2 GEMM + min/max over k --
// Shared buffers are declared ONCE in the kernel and passed in, so the two
// template instantiations don't double the static smem (ptxas sums them).
template<int K>
__device__ __forceinline__ void conv2_body(float* __restrict__ Ws,
                                           float* __restrict__ Ub,
                                           float* __restrict__ bnsc,
                                           float* __restrict__ bnsh,
                                           float* __restrict__ blockS,
                                           float* __restrict__ blockSS)
{
    const int si = (K==6) ? 0 : 1;
    const float* __restrict__ P   = g_PQ[si*2];
    const float* __restrict__ Q   = g_PQ[si*2 + 1];
    const float* __restrict__ W2t = g_W2t[si];
    float* __restrict__ part = g_part + si*G_CONV*128;
    const int bnoff = si*128;
    const int nTiles = (NPTS*K)/MT;
    const int PPT = MT/K;

    int t = threadIdx.x;
    for (int i = t; i < 4096; i += 128) Ws[i] = W2t[i];
    if (t < 64) { bnsc[t] = g_bnA[bnoff + t]; bnsh[t] = g_bnA[bnoff + 64 + t]; }
    __syncthreads();

    int tx = t & 15, ty = t >> 4;
    float accS[8], accSS[8];
#pragma unroll
    for (int i = 0; i < 8; i++) { accS[i] = 0.f; accSS[i] = 0.f; }

    for (int tile = blockIdx.x; tile < nTiles; tile += G_CONV) {
        int mbase = tile * MT;
        __syncthreads();
        for (int u = t; u < 2*MT; u += 128) {
            int e = u >> 1, h = u & 1;
            int m = mbase + e;
            int kk = m % K, bn = m / K;
            int j  = g_idx[bn*KLn + kk];
            int b  = bn >> 13;
            const float4* Pp = (const float4*)&P[bn*64 + h*32];
            const float4* Qp = (const float4*)&Q[(b*NN + j)*64 + h*32];
#pragma unroll
            for (int c4 = 0; c4 < 8; c4++) {
                float4 pv = Pp[c4], qv = Qp[c4];
                int c = h*32 + c4*4;
                Ub[(c+0)*97 + e] = fmaxf(0.f, fmaf(pv.x+qv.x, bnsc[c+0], bnsh[c+0]));
                Ub[(c+1)*97 + e] = fmaxf(0.f, fmaf(pv.y+qv.y, bnsc[c+1], bnsh[c+1]));
                Ub[(c+2)*97 + e] = fmaxf(0.f, fmaf(pv.z+qv.z, bnsc[c+2], bnsh[c+2]));
                Ub[(c+3)*97 + e] = fmaxf(0.f, fmaf(pv.w+qv.w, bnsc[c+3], bnsh[c+3]));
            }
        }
        __syncthreads();

        unsigned long long acc2[4][6];
#pragma unroll
        for (int i = 0; i < 4; i++)
#pragma unroll
            for (int j2 = 0; j2 < 6; j2++) acc2[i][j2] = 0ULL;

#pragma unroll 8
        for (int k = 0; k < 64; k++) {
            const unsigned long long* ap = (const unsigned long long*)&Ws[k*64 + ty*8];
            unsigned long long a2[4] = {ap[0], ap[1], ap[2], ap[3]};
            unsigned long long b2[6];
#pragma unroll
            for (int mi = 0; mi < 6; mi++)
                b2[mi] = dup2(Ub[k*97 + tx + 16*mi]);
#pragma unroll
            for (int oi = 0; oi < 4; oi++)
#pragma unroll
                for (int mi = 0; mi < 6; mi++)
                    acc2[oi][mi] = ffma2(a2[oi], b2[mi], acc2[oi][mi]);
        }
        __syncthreads();

#pragma unroll
        for (int mi = 0; mi < 6; mi++) {
            int e = tx + 16*mi;
            float v[8];
#pragma unroll
            for (int oi = 0; oi < 4; oi++) upk2(acc2[oi][mi], v[2*oi], v[2*oi+1]);
#pragma unroll
            for (int oi = 0; oi < 8; oi++) {
                accS[oi]  += v[oi];
                accSS[oi] = fmaf(v[oi], v[oi], accSS[oi]);
            }
#pragma unroll
            for (int oi = 0; oi < 4; oi++)
                *(float2*)&Ub[e*66 + ty*8 + 2*oi] = make_float2(v[2*oi], v[2*oi+1]);
        }
        __syncthreads();

        for (int s = t; s < PPT*64; s += 128) {
            int p = s >> 6, ch = s & 63;
            float vmax = -3.4e38f, vmin = 3.4e38f;
#pragma unroll
            for (int kk = 0; kk < K; kk++) {
                float v = Ub[(p*K + kk)*66 + ch];
                vmax = fmaxf(vmax, v); vmin = fminf(vmin, v);
            }
            int pt = mbase/K + p;
            g_mx[si][pt*64 + ch] = vmax;
            g_mn[si][pt*64 + ch] = vmin;
        }
    }

#pragma unroll
    for (int off = 1; off < 16; off <<= 1)
#pragma unroll
        for (int oi = 0; oi < 8; oi++) {
            accS[oi]  += __shfl_xor_sync(0xffffffffu, accS[oi],  off);
            accSS[oi] += __shfl_xor_sync(0xffffffffu, accSS[oi], off);
        }
    if (tx == 0)
#pragma unroll
        for (int oi = 0; oi < 8; oi++) { blockS[ty*8+oi] = accS[oi]; blockSS[ty*8+oi] = accSS[oi]; }
    __syncthreads();
    if (t < 128)
        part[blockIdx.x*128 + t] = (t < 64) ? blockS[t] : blockSS[t-64];
}
__global__ __launch_bounds__(128) void k_convF()
{
    __shared__ __align__(16) float Ws[4096];
    __shared__ __align__(16) float Ub[6336];
    __shared__ float bnsc[64], bnsh[64];
    __shared__ float blockS[64], blockSS[64];
    if (blockIdx.y == 0) conv2_body<6> (Ws, Ub, bnsc, bnsh, blockS, blockSS);
    else                 conv2_body<12>(Ws, Ub, bnsc, bnsh, blockS, blockSS);
}

// ---------------- fused BN2 + ReLU + max -> output (both streams) -----------
__global__ __launch_bounds__(256) void k_outF(float* __restrict__ out)
{
    int y = blockIdx.y;                        // 0 = s (ch 0..63), 1 = l (64..127)
    const int chOff = y * 64;
    const float* mx = g_mx[y];
    const float* mn = g_mn[y];
    __shared__ float res[64][33];
    int t = threadIdx.x;
    int warp = t >> 5, lane = t & 31;
    int bn0 = blockIdx.x * 32;
    int b = bn0 >> 13, n0 = bn0 & (NN-1);
    float sc0 = g_bnB[y*128 + lane],      sh0 = g_bnB[y*128 + 64 + lane];
    float sc1 = g_bnB[y*128 + lane + 32], sh1 = g_bnB[y*128 + 96 + lane];
#pragma unroll
    for (int i = 0; i < 4; i++) {
        int nl = warp*4 + i;
        int pt = bn0 + nl;
        float h0 = (sc0 >= 0.f) ? mx[pt*64 + lane]      : mn[pt*64 + lane];
        float h1 = (sc1 >= 0.f) ? mx[pt*64 + lane + 32] : mn[pt*64 + lane + 32];
        res[lane][nl]      = fmaxf(0.f, fmaf(h0, sc0, sh0));
        res[lane + 32][nl] = fmaxf(0.f, fmaf(h1, sc1, sh1));
    }
    __syncthreads();
#pragma unroll
    for (int i = 0; i < 8; i++) {
        int id = t + i*256;
        int r = id >> 5, col = id & 31;
        out[((size_t)b*128 + chOff + r)*NN + n0 + col] = res[r][col];
    }
}

// ---------------- launch ----------------
extern "C" void kernel_launch(void* const* d_in, const int* in_sizes, int n_in,
                              void* d_out, int out_size)
{
    const float* x    = (const float*)d_in[0];
    const float* pos  = (const float*)d_in[1];
    const float* Ws1  = (const float*)d_in[2];
    const float* gs1  = (const float*)d_in[4];
    const float* ts1  = (const float*)d_in[5];
    const float* Ws2  = (const float*)d_in[6];
    const float* gs2  = (const float*)d_in[8];
    const float* ts2  = (const float*)d_in[9];
    const float* Wl1  = (const float*)d_in[10];
    const float* gl1  = (const float*)d_in[12];
    const float* tl1  = (const float*)d_in[13];
    const float* Wl2  = (const float*)d_in[14];
    const float* gl2  = (const float*)d_in[16];
    const float* tl2  = (const float*)d_in[17];
    float* out = (float*)d_out;

    k_prep<<<16, 256>>>(Ws1, Wl1, Ws2, Wl2);
    k_pos<<<NPTS/256, 256>>>(pos);
    k_pack<<<dim3(NN/32, 2, BB), 256>>>(x);
    k_knn1<<<NPTS/64, 256>>>();
    k_knn3<<<NPTS/256, 256>>>();
    k_pq<<<dim3(NPTS/64, 4), 128>>>();

    k_statsF<<<dim3(G_STAT, 2), 256>>>();
    k_reduceF<<<2, 256>>>(G_STAT, G_STAT*128,
                          1.f/(NPTS*6.f), 1.f/(NPTS*12.f),
                          gs1, ts1, gl1, tl1, 0);
    k_convF<<<dim3(G_CONV, 2), 128>>>();
    k_reduceF<<<2, 256>>>(G_CONV, G_CONV*128,
                          1.f/(NPTS*6.f), 1.f/(NPTS*12.f),
                          gs2, ts2, gl2, tl2, 1);
    k_outF<<<dim3(NPTS/32, 2), 256>>>(out);
}

// round 14
// speedup vs baseline: 2.8720x; 1.0480x over previous
#include <cuda_runtime.h>

#define BB   4
#define NN   8192
#define CCH  64
#define NPTS (BB*NN)          // 32768
#define KLn  12
#define EPSbn 1e-5f
#define G_STAT 1024
#define G_CONV 1184
#define MT   96               // conv2 edge-tile (divisible by 6 and 12)
#define KCH  1024             // knn shared chunk (float4 count)
#define HALFN 4096            // candidates per knn thread (TPQ=2)

// ---------------- scratch (static device arrays; no allocation) ----------------
__device__ __align__(16) float  g_xt[NPTS*CCH];            // x transposed (B,N,C)   8MB
__device__ __align__(16) float4 g_pp[NPTS];                // packed points (x,y,z,|p|^2)
__device__             int    g_idx[NPTS*KLn];             // 12 NN per point
__device__ __align__(16) float g_PQ[4][NPTS*CCH];          // P_s,Q_s,P_l,Q_l        32MB
__device__ __align__(16) float g_mx[2][NPTS*CCH];          // per-stream h2 max     16MB
__device__ __align__(16) float g_mn[2][NPTS*CCH];          // per-stream h2 min     16MB
__device__             float  g_part[2*1184*128];          // per-stream block stats
__device__             float  g_bnA[256];                  // layer1 scale/shift (s,l)
__device__             float  g_bnB[256];                  // layer2 scale/shift (s,l)
__device__ __align__(16) float g_Wf[4][4096];              // folded conv1 W, [k][o]
__device__ __align__(16) float g_W2t[2][4096];             // conv2 W transposed [k][o]

// ---------------- f32x2 helpers ----------------
__device__ __forceinline__ unsigned long long pk2(float lo, float hi) {
    unsigned long long r;
    asm("mov.b64 %0, {%1,%2};" : "=l"(r) : "f"(lo), "f"(hi));
    return r;
}
__device__ __forceinline__ unsigned long long dup2(float v) { return pk2(v, v); }
__device__ __forceinline__ void upk2(unsigned long long r, float& lo, float& hi) {
    asm("mov.b64 {%0,%1}, %2;" : "=f"(lo), "=f"(hi) : "l"(r));
}
__device__ __forceinline__ unsigned long long ffma2(unsigned long long a,
                                                    unsigned long long b,
                                                    unsigned long long c) {
    unsigned long long d;
    asm("fma.rn.f32x2 %0, %1, %2, %3;" : "=l"(d) : "l"(a), "l"(b), "l"(c));
    return d;
}

// monotone float->u32 (total order preserving, handles negatives)
__device__ __forceinline__ unsigned fmono(float f) {
    unsigned u = __float_as_uint(f);
    return u ^ ((u >> 31) ? 0xFFFFFFFFu : 0x80000000u);
}

// ---------------- weight prep: fold conv1, transpose everything ----------------
__global__ void k_prep(const float* __restrict__ Ws1, const float* __restrict__ Wl1,
                       const float* __restrict__ Ws2, const float* __restrict__ Wl2)
{
    int t = blockIdx.x*blockDim.x + threadIdx.x;
    if (t < 4096) {
        int o = t >> 6, c = t & 63;
        float a0 = Ws1[o*128 + c],  a1 = Ws1[o*128 + 64 + c];
        g_Wf[0][c*64+o] = a0 - a1;          // Wa_s
        g_Wf[1][c*64+o] = a1;               // Wb_s
        float b0 = Wl1[o*128 + c],  b1 = Wl1[o*128 + 64 + c];
        g_Wf[2][c*64+o] = b0 - b1;          // Wa_l
        g_Wf[3][c*64+o] = b1;               // Wb_l
        g_W2t[0][c*64+o] = Ws2[o*64+c];
        g_W2t[1][c*64+o] = Wl2[o*64+c];
    }
}

// ---------------- pack pos into float4 ----------------
__global__ void k_pos(const float* __restrict__ pos)
{
    int t = blockIdx.x*blockDim.x + threadIdx.x;
    if (t < NPTS) {
        int n = t & (NN-1), b = t >> 13;
        float px = pos[(b*3+0)*NN + n];
        float py = pos[(b*3+1)*NN + n];
        float pz = pos[(b*3+2)*NN + n];
        g_pp[t] = make_float4(px, py, pz, px*px + py*py + pz*pz);
    }
}

// ---------------- coalesced tiled transpose of x ----------------
__global__ __launch_bounds__(256) void k_pack(const float* __restrict__ x)
{
    __shared__ float tile[32][33];
    int b  = blockIdx.z;
    int c0 = blockIdx.y * 32;
    int n0 = blockIdx.x * 32;
    int tx = threadIdx.x & 31, ty = threadIdx.x >> 5;   // ty 0..7
#pragma unroll
    for (int i = 0; i < 4; i++) {
        int r = ty + 8*i;                               // channel row
        tile[r][tx] = x[((size_t)(b*CCH + c0 + r))*NN + n0 + tx];
    }
    __syncthreads();
#pragma unroll
    for (int i = 0; i < 4; i++) {
        int r = ty + 8*i;                               // n row
        g_xt[((size_t)(b*NN + n0 + r))*64 + c0 + tx] = tile[tx][r];
    }
}

// ---------------- KNN, TPQ=2, fully fused: scan + merge + emit + select ----
// Phase A: branch-free FMNMX chain keeps the 13 smallest dists (sorted), in
//   the shifted metric d~ = d^2 - |q|^2.
// Merge:   merge-path of the two sorted half-lists -> exact global 13th (thr).
// Phase B: identical distance recomputation; accept d <= thr, emit u64
//   (dist,idx) keys into SHARED (aliased over the dead merge buffer).
// Select:  threads 0..63 pick the 12 smallest of 26 keys, write g_idx.
#define KINS(dv)                                                   \
    if ((dv) < bd[12]) {                                           \
        float tt = (dv);                                           \
        _Pragma("unroll")                                          \
        for (int jj = 0; jj < 13; jj++) {                          \
            float lo = fminf(bd[jj], tt);                          \
            tt = fmaxf(bd[jj], tt);                                \
            bd[jj] = lo;                                           \
        }                                                          \
    }

__global__ __launch_bounds__(128) void k_knnA()
{
    __shared__ __align__(16) float4 tA[KCH];     // 16KB tile, lower half
    __shared__ __align__(16) float4 tB[KCH];     // 16KB tile, upper half
    __shared__ __align__(16) unsigned long long keys[64][26];  // 13.3KB
    __shared__ float thrS[64];
    float* sA = (float*)&keys[0][0];             // alias: 128*13 floats = 6.7KB
                                                 // (dead before keys written)
    int t  = threadIdx.x;
    int ql = t & 63, h = t >> 6;                 // query lane, half
    int q  = blockIdx.x*64 + ql;
    int b  = q >> 13;
    int nself = q & (NN-1);
    float4 qp = g_pp[q];
    float qx = -2.f*qp.x, qy = -2.f*qp.y, qz = -2.f*qp.z;
    float4* tile = h ? tB : tA;
    int hbase = b*NN + h*HALFN;

    float bd[13];
#pragma unroll
    for (int i = 0; i < 13; i++) bd[i] = 3.4e38f;

    // ---- phase A: per-half top-13 distances ----
    for (int cb = 0; cb < HALFN; cb += KCH) {
        __syncthreads();
        for (int i = ql; i < KCH; i += 64)
            tile[i] = g_pp[hbase + cb + i];
        __syncthreads();
#pragma unroll 1
        for (int c0 = 0; c0 < KCH; c0 += 8) {
            float d[8];
#pragma unroll
            for (int u = 0; u < 8; u++) {
                float4 p = tile[c0+u];
                d[u] = fmaf(qx,p.x, fmaf(qy,p.y, fmaf(qz,p.z, p.w)));
            }
            float m = fminf(fminf(fminf(d[0],d[1]), fminf(d[2],d[3])),
                            fminf(fminf(d[4],d[5]), fminf(d[6],d[7])));
            if (m < bd[12]) {
                KINS(d[0]); KINS(d[1]); KINS(d[2]); KINS(d[3]);
                KINS(d[4]); KINS(d[5]); KINS(d[6]); KINS(d[7]);
            }
        }
    }

    // ---- publish sorted half-lists, merge-path to global 13th (thr) ----
#pragma unroll
    for (int r = 0; r < 13; r++) sA[t*13 + r] = bd[r];
    __syncthreads();
    if (t < 64) {
        const float* A  = &sA[t*13];
        const float* Bv = &sA[(t+64)*13];
        int i = 0, j = 0; float v = 0.f;
#pragma unroll
        for (int s = 0; s < 13; s++) {
            float a = A[i], bb = Bv[j];
            if (a <= bb) { v = a; i++; } else { v = bb; j++; }
        }
        thrS[t] = v;
    }
    __syncthreads();
    float thr = thrS[ql];                        // read BEFORE keys overwrite sA

    // ---- phase B: emit u64 keys for d <= thr, excluding self ----
    int cnt = 0;
    for (int cb = 0; cb < HALFN; cb += KCH) {
        __syncthreads();
        for (int i = ql; i < KCH; i += 64)
            tile[i] = g_pp[hbase + cb + i];
        __syncthreads();
#pragma unroll 1
        for (int c0 = 0; c0 < KCH; c0 += 8) {
            float d[8];
#pragma unroll
            for (int u = 0; u < 8; u++) {
                float4 p = tile[c0+u];
                d[u] = fmaf(qx,p.x, fmaf(qy,p.y, fmaf(qz,p.z, p.w)));
            }
            float m = fminf(fminf(fminf(d[0],d[1]), fminf(d[2],d[3])),
                            fminf(fminf(d[4],d[5]), fminf(d[6],d[7])));
            if (m <= thr) {
#pragma unroll
                for (int u = 0; u < 8; u++) {
                    if (d[u] <= thr) {
                        int j = h*HALFN + cb + c0 + u;
                        if (j != nself && cnt < 13) {
                            keys[ql][h*13 + cnt] =
                                ((unsigned long long)fmono(d[u]) << 13)
                                | (unsigned)j;
                            cnt++;
                        }
                    }
                }
            }
        }
    }
#pragma unroll 1
    for (int r = cnt; r < 13; r++)
        keys[ql][h*13 + r] = ~0ULL;              // pad
    __syncthreads();

    // ---- final select: 12 smallest of 26 keys, write g_idx directly ----
    if (t < 64) {
        unsigned long long best[12];
#pragma unroll
        for (int r = 0; r < 12; r++) best[r] = ~0ULL;
#pragma unroll 1
        for (int r = 0; r < 26; r++) {
            unsigned long long key = keys[t][r];
            if (key < best[11]) {
                unsigned long long tt = key;
#pragma unroll
                for (int j = 0; j < 12; j++) {
                    unsigned long long lo = (best[j] < tt) ? best[j] : tt;
                    unsigned long long hi = (best[j] < tt) ? tt : best[j];
                    best[j] = lo; tt = hi;
                }
            }
        }
        int qq = blockIdx.x*64 + t;
#pragma unroll
        for (int r = 0; r < 12; r++)
            g_idx[qq*KLn + r] = (int)(best[r] & 8191u);
    }
}

// ---------------- P/Q GEMM with f32x2 FMA ----------------
__global__ __launch_bounds__(128) void k_pq()
{
    __shared__ __align__(16) float Ws[4096];
    __shared__ __align__(16) float Us[4096];
    int w = blockIdx.y;
    int t = threadIdx.x;
    for (int i = t; i < 4096; i += 128) Ws[i] = g_Wf[w][i];

    int base = blockIdx.x * 64;
    {   // stage X tile k-major with xor swizzle
        int e = t >> 1, h = t & 1;
        const float4* src = (const float4*)&g_xt[(base + e)*64 + h*32];
        int gg = e >> 2, eo = e & 3;
#pragma unroll
        for (int c4 = 0; c4 < 8; c4++) {
            float4 v = src[c4];
            int c = h*32 + c4*4;
            Us[(c+0)*64 + ((gg ^ ((c+0)&15))<<2) + eo] = v.x;
            Us[(c+1)*64 + ((gg ^ ((c+1)&15))<<2) + eo] = v.y;
            Us[(c+2)*64 + ((gg ^ ((c+2)&15))<<2) + eo] = v.z;
            Us[(c+3)*64 + ((gg ^ ((c+3)&15))<<2) + eo] = v.w;
        }
    }
    __syncthreads();

    int tx = t & 15, ty = t >> 4;
    unsigned long long acc2[4][4];             // [oi-pair][mi]
#pragma unroll
    for (int i = 0; i < 4; i++)
#pragma unroll
        for (int j = 0; j < 4; j++) acc2[i][j] = 0ULL;

#pragma unroll 8
    for (int k = 0; k < 64; k++) {
        const unsigned long long* ap = (const unsigned long long*)&Ws[k*64 + ty*8];
        unsigned long long a2[4] = {ap[0], ap[1], ap[2], ap[3]};
        float4 bf = *(const float4*)&Us[k*64 + ((tx ^ (k&15))<<2)];
        unsigned long long b2[4] = {dup2(bf.x), dup2(bf.y), dup2(bf.z), dup2(bf.w)};
#pragma unroll
        for (int oi = 0; oi < 4; oi++)
#pragma unroll
            for (int mi = 0; mi < 4; mi++)
                acc2[oi][mi] = ffma2(a2[oi], b2[mi], acc2[oi][mi]);
    }

    float* out = g_PQ[w];
#pragma unroll
    for (int mi = 0; mi < 4; mi++) {
        float a[8];
#pragma unroll
        for (int oi = 0; oi < 4; oi++) upk2(acc2[oi][mi], a[2*oi], a[2*oi+1]);
        int pt = base + tx*4 + mi;
        *(float4*)&out[pt*64 + ty*8]     = make_float4(a[0],a[1],a[2],a[3]);
        *(float4*)&out[pt*64 + ty*8 + 4] = make_float4(a[4],a[5],a[6],a[7]);
    }
}

// ---------------- fused stats of h1 = P[i]+Q[j] (both streams) -------------
template<int K>
__device__ __forceinline__ void stats_body(const float* __restrict__ P,
                                           const float* __restrict__ Q,
                                           float* __restrict__ part,
                                           float (*stg)[128])
{
    const int M = NPTS*K;
    int warp = threadIdx.x >> 5, lane = threadIdx.x & 31;
    int gw = blockIdx.x*8 + warp, nw = G_STAT*8;
    float s0=0, ss0=0, s1=0, ss1=0;
    for (int m = gw; m < M; m += nw) {
        int kk = m % K, bn = m / K;
        int j  = g_idx[bn*KLn + kk];
        int b  = bn >> 13;
        const float* Pp = &P[bn*64];
        const float* Qp = &Q[(b*NN + j)*64];
        float v0 = Pp[lane]      + Qp[lane];
        float v1 = Pp[lane + 32] + Qp[lane + 32];
        s0 += v0; ss0 = fmaf(v0, v0, ss0);
        s1 += v1; ss1 = fmaf(v1, v1, ss1);
    }
    stg[warp][lane]      = s0;  stg[warp][64+lane] = ss0;
    stg[warp][32+lane]   = s1;  stg[warp][96+lane] = ss1;
    __syncthreads();
    int t = threadIdx.x;
    if (t < 128) {
        float a = 0;
#pragma unroll
        for (int w2 = 0; w2 < 8; w2++) a += stg[w2][t];
        part[blockIdx.x*128 + t] = a;
    }
}
__global__ __launch_bounds__(256) void k_statsF()
{
    __shared__ float stg[8][128];
    if (blockIdx.y == 0) stats_body<6> (g_PQ[0], g_PQ[1], g_part, stg);
    else                 stats_body<12>(g_PQ[2], g_PQ[3], g_part + G_STAT*128, stg);
}

// ---------------- fused BN finalize (both streams, one layer) --------------
__global__ __launch_bounds__(256) void k_reduceF(int G, int partStride,
                         float invM0, float invM1,
                         const float* __restrict__ g0, const float* __restrict__ t0,
                         const float* __restrict__ g1, const float* __restrict__ t1,
                         int which)
{
    __shared__ float sm[8][64];
    int y = blockIdx.x;                        // stream 0=s, 1=l
    const float* part = g_part + y*partStride;
    float invM = y ? invM1 : invM0;
    const float* gamma = y ? g1 : g0;
    const float* beta  = y ? t1 : t0;
    int t = threadIdx.x;
    int c = t & 63, grp = t >> 6;              // 4 groups
    int chunk = (G + 3) >> 2;
    int gg0 = grp*chunk, gg1 = min(G, gg0 + chunk);
    float S = 0.f, SS = 0.f;
    for (int g = gg0; g < gg1; g++) { S += part[g*128 + c]; SS += part[g*128 + 64 + c]; }
    sm[grp][c] = S; sm[4+grp][c] = SS;
    __syncthreads();
    if (t < 64) {
        float Sa = 0.f, SSa = 0.f;
#pragma unroll
        for (int g = 0; g < 4; g++) { Sa += sm[g][t]; SSa += sm[4+g][t]; }
        float mean = Sa * invM;
        float var  = SSa * invM - mean*mean;
        float sc   = gamma[t] * rsqrtf(var + EPSbn);
        float sh   = beta[t] - mean*sc;
        float* dst = (which ? g_bnB : g_bnA) + y*128;
        dst[t] = sc; dst[64+t] = sh;
    }
}

// ---------------- fused conv2 (both streams): f32x2 GEMM + min/max over k --
// Shared buffers declared ONCE in the kernel and passed in (ptxas sums
// per-instantiation statics otherwise).
template<int K>
__device__ __forceinline__ void conv2_body(float* __restrict__ Ws,
                                           float* __restrict__ Ub,
                                           float* __restrict__ bnsc,
                                           float* __restrict__ bnsh,
                                           float* __restrict__ blockS,
                                           float* __restrict__ blockSS)
{
    const int si = (K==6) ? 0 : 1;
    const float* __restrict__ P   = g_PQ[si*2];
    const float* __restrict__ Q   = g_PQ[si*2 + 1];
    const float* __restrict__ W2t = g_W2t[si];
    float* __restrict__ part = g_part + si*G_CONV*128;
    const int bnoff = si*128;
    const int nTiles = (NPTS*K)/MT;
    const int PPT = MT/K;

    int t = threadIdx.x;
    for (int i = t; i < 4096; i += 128) Ws[i] = W2t[i];
    if (t < 64) { bnsc[t] = g_bnA[bnoff + t]; bnsh[t] = g_bnA[bnoff + 64 + t]; }
    __syncthreads();

    int tx = t & 15, ty = t >> 4;
    float accS[8], accSS[8];
#pragma unroll
    for (int i = 0; i < 8; i++) { accS[i] = 0.f; accSS[i] = 0.f; }

    for (int tile = blockIdx.x; tile < nTiles; tile += G_CONV) {
        int mbase = tile * MT;
        __syncthreads();
        for (int u = t; u < 2*MT; u += 128) {
            int e = u >> 1, h = u & 1;
            int m = mbase + e;
            int kk = m % K, bn = m / K;
            int j  = g_idx[bn*KLn + kk];
            int b  = bn >> 13;
            const float4* Pp = (const float4*)&P[bn*64 + h*32];
            const float4* Qp = (const float4*)&Q[(b*NN + j)*64 + h*32];
#pragma unroll
            for (int c4 = 0; c4 < 8; c4++) {
                float4 pv = Pp[c4], qv = Qp[c4];
                int c = h*32 + c4*4;
                Ub[(c+0)*97 + e] = fmaxf(0.f, fmaf(pv.x+qv.x, bnsc[c+0], bnsh[c+0]));
                Ub[(c+1)*97 + e] = fmaxf(0.f, fmaf(pv.y+qv.y, bnsc[c+1], bnsh[c+1]));
                Ub[(c+2)*97 + e] = fmaxf(0.f, fmaf(pv.z+qv.z, bnsc[c+2], bnsh[c+2]));
                Ub[(c+3)*97 + e] = fmaxf(0.f, fmaf(pv.w+qv.w, bnsc[c+3], bnsh[c+3]));
            }
        }
        __syncthreads();

        unsigned long long acc2[4][6];
#pragma unroll
        for (int i = 0; i < 4; i++)
#pragma unroll
            for (int j2 = 0; j2 < 6; j2++) acc2[i][j2] = 0ULL;

#pragma unroll 8
        for (int k = 0; k < 64; k++) {
            const unsigned long long* ap = (const unsigned long long*)&Ws[k*64 + ty*8];
            unsigned long long a2[4] = {ap[0], ap[1], ap[2], ap[3]};
            unsigned long long b2[6];
#pragma unroll
            for (int mi = 0; mi < 6; mi++)
                b2[mi] = dup2(Ub[k*97 + tx + 16*mi]);
#pragma unroll
            for (int oi = 0; oi < 4; oi++)
#pragma unroll
                for (int mi = 0; mi < 6; mi++)
                    acc2[oi][mi] = ffma2(a2[oi], b2[mi], acc2[oi][mi]);
        }
        __syncthreads();

#pragma unroll
        for (int mi = 0; mi < 6; mi++) {
            int e = tx + 16*mi;
            float v[8];
#pragma unroll
            for (int oi = 0; oi < 4; oi++) upk2(acc2[oi][mi], v[2*oi], v[2*oi+1]);
#pragma unroll
            for (int oi = 0; oi < 8; oi++) {
                accS[oi]  += v[oi];
                accSS[oi] = fmaf(v[oi], v[oi], accSS[oi]);
            }
#pragma unroll
            for (int oi = 0; oi < 4; oi++)
                *(float2*)&Ub[e*66 + ty*8 + 2*oi] = make_float2(v[2*oi], v[2*oi+1]);
        }
        __syncthreads();

        for (int s = t; s < PPT*64; s += 128) {
            int p = s >> 6, ch = s & 63;
            float vmax = -3.4e38f, vmin = 3.4e38f;
#pragma unroll
            for (int kk = 0; kk < K; kk++) {
                float v = Ub[(p*K + kk)*66 + ch];
                vmax = fmaxf(vmax, v); vmin = fminf(vmin, v);
            }
            int pt = mbase/K + p;
            g_mx[si][pt*64 + ch] = vmax;
            g_mn[si][pt*64 + ch] = vmin;
        }
    }

#pragma unroll
    for (int off = 1; off < 16; off <<= 1)
#pragma unroll
        for (int oi = 0; oi < 8; oi++) {
            accS[oi]  += __shfl_xor_sync(0xffffffffu, accS[oi],  off);
            accSS[oi] += __shfl_xor_sync(0xffffffffu, accSS[oi], off);
        }
    if (tx == 0)
#pragma unroll
        for (int oi = 0; oi < 8; oi++) { blockS[ty*8+oi] = accS[oi]; blockSS[ty*8+oi] = accSS[oi]; }
    __syncthreads();
    if (t < 128)
        part[blockIdx.x*128 + t] = (t < 64) ? blockS[t] : blockSS[t-64];
}
__global__ __launch_bounds__(128) void k_convF()
{
    __shared__ __align__(16) float Ws[4096];
    __shared__ __align__(16) float Ub[6336];
    __shared__ float bnsc[64], bnsh[64];
    __shared__ float blockS[64], blockSS[64];
    if (blockIdx.y == 0) conv2_body<6> (Ws, Ub, bnsc, bnsh, blockS, blockSS);
    else                 conv2_body<12>(Ws, Ub, bnsc, bnsh, blockS, blockSS);
}

// ---------------- fused BN2 + ReLU + max -> output (both streams) -----------
__global__ __launch_bounds__(256) void k_outF(float* __restrict__ out)
{
    int y = blockIdx.y;                        // 0 = s (ch 0..63), 1 = l (64..127)
    const int chOff = y * 64;
    const float* mx = g_mx[y];
    const float* mn = g_mn[y];
    __shared__ float res[64][33];
    int t = threadIdx.x;
    int warp = t >> 5, lane = t & 31;
    int bn0 = blockIdx.x * 32;
    int b = bn0 >> 13, n0 = bn0 & (NN-1);
    float sc0 = g_bnB[y*128 + lane],      sh0 = g_bnB[y*128 + 64 + lane];
    float sc1 = g_bnB[y*128 + lane + 32], sh1 = g_bnB[y*128 + 96 + lane];
#pragma unroll
    for (int i = 0; i < 4; i++) {
        int nl = warp*4 + i;
        int pt = bn0 + nl;
        float h0 = (sc0 >= 0.f) ? mx[pt*64 + lane]      : mn[pt*64 + lane];
        float h1 = (sc1 >= 0.f) ? mx[pt*64 + lane + 32] : mn[pt*64 + lane + 32];
        res[lane][nl]      = fmaxf(0.f, fmaf(h0, sc0, sh0));
        res[lane + 32][nl] = fmaxf(0.f, fmaf(h1, sc1, sh1));
    }
    __syncthreads();
#pragma unroll
    for (int i = 0; i < 8; i++) {
        int id = t + i*256;
        int r = id >> 5, col = id & 31;
        out[((size_t)b*128 + chOff + r)*NN + n0 + col] = res[r][col];
    }
}

// ---------------- launch ----------------
extern "C" void kernel_launch(void* const* d_in, const int* in_sizes, int n_in,
                              void* d_out, int out_size)
{
    const float* x    = (const float*)d_in[0];
    const float* pos  = (const float*)d_in[1];
    const float* Ws1  = (const float*)d_in[2];
    const float* gs1  = (const float*)d_in[4];
    const float* ts1  = (const float*)d_in[5];
    const float* Ws2  = (const float*)d_in[6];
    const float* gs2  = (const float*)d_in[8];
    const float* ts2  = (const float*)d_in[9];
    const float* Wl1  = (const float*)d_in[10];
    const float* gl1  = (const float*)d_in[12];
    const float* tl1  = (const float*)d_in[13];
    const float* Wl2  = (const float*)d_in[14];
    const float* gl2  = (const float*)d_in[16];
    const float* tl2  = (const float*)d_in[17];
    float* out = (float*)d_out;

    k_prep<<<16, 256>>>(Ws1, Wl1, Ws2, Wl2);
    k_pos<<<NPTS/256, 256>>>(pos);
    k_pack<<<dim3(NN/32, 2, BB), 256>>>(x);
    k_knnA<<<NPTS/64, 128>>>();
    k_pq<<<dim3(NPTS/64, 4), 128>>>();

    k_statsF<<<dim3(G_STAT, 2), 256>>>();
    k_reduceF<<<2, 256>>>(G_STAT, G_STAT*128,
                          1.f/(NPTS*6.f), 1.f/(NPTS*12.f),
                          gs1, ts1, gl1, tl1, 0);
    k_convF<<<dim3(G_CONV, 2), 128>>>();
    k_reduceF<<<2, 256>>>(G_CONV, G_CONV*128,
                          1.f/(NPTS*6.f), 1.f/(NPTS*12.f),
                          gs2, ts2, gl2, tl2, 1);
    k_outF<<<dim3(NPTS/32, 2), 256>>>(out);
}